// round 3
// baseline (speedup 1.0000x reference)
#include <cuda_runtime.h>

#define B_DIM 256
#define M_DIM 4096
#define C_DIM 9
#define BLK 256
#define ROW_BLOCKS 256
#define RECON_BLOCKS 188
#define RECON_N4 (256 * 128 * 128 / 4) /* 1048576 float4 */
#define EPSF 1e-7f

// Accumulators: 0=coord_num, 1=width_num, 2=n_valid, 3=bce(log2 units), 4=cont, 5=recon_sq
__device__ double g_acc[6];

__global__ void zero_kernel() {
    if (threadIdx.x < 6) g_acc[threadIdx.x] = 0.0;
}

__global__ void __launch_bounds__(BLK) fused_kernel(
    const float* __restrict__ pred,
    const float* __restrict__ tgt,
    const float* __restrict__ rec,
    const float* __restrict__ img)
{
    __shared__ unsigned char  s_fmask[M_DIM];   // 4 KB
    __shared__ unsigned short s_rank[M_DIM];    // 8 KB
    __shared__ float2         s_comp[M_DIM];    // 32 KB
    __shared__ int   s_wsum[BLK / 32];
    __shared__ float s_red[BLK / 32];
    __shared__ int   s_total;

    const int tid = threadIdx.x;

    // ---------------- Recon-MSE blocks (bid >= ROW_BLOCKS) ----------------
    if (blockIdx.x >= ROW_BLOCKS) {
        const int rb = blockIdx.x - ROW_BLOCKS;
        const float4* r4 = (const float4*)rec;
        const float4* i4 = (const float4*)img;
        float acc = 0.f;
        for (int i = rb * BLK + tid; i < RECON_N4; i += RECON_BLOCKS * BLK) {
            float4 a = __ldg(r4 + i);
            float4 b = __ldg(i4 + i);
            float d0 = a.x - b.x, d1 = a.y - b.y, d2 = a.z - b.z, d3 = a.w - b.w;
            acc = fmaf(d0, d0, acc);
            acc = fmaf(d1, d1, acc);
            acc = fmaf(d2, d2, acc);
            acc = fmaf(d3, d3, acc);
        }
        #pragma unroll
        for (int o = 16; o; o >>= 1) acc += __shfl_down_sync(0xFFFFFFFFu, acc, o);
        if ((tid & 31) == 0) s_red[tid >> 5] = acc;
        __syncthreads();
        if (tid == 0) {
            float s = 0.f;
            #pragma unroll
            for (int w = 0; w < BLK / 32; w++) s += s_red[w];
            atomicAdd(&g_acc[5], (double)s);
        }
        return;
    }

    // ---------------- Row blocks: one CTA per batch row --------------------
    const int row = blockIdx.x;
    const float* prow = pred + (size_t)row * M_DIM * C_DIM;
    const float* trow = tgt  + (size_t)row * M_DIM * C_DIM;

    // Pass 1: validity mask + block prefix scan -> ranks for compaction.
    const int pbase = tid * 16;
    int cnt = 0;
    #pragma unroll
    for (int j = 0; j < 16; j++) {
        float t8 = __ldg(trow + (pbase + j) * 9 + 8);
        int m = (t8 > 0.5f) ? 1 : 0;
        s_fmask[pbase + j] = (unsigned char)m;
        cnt += m;
    }
    const int lane = tid & 31, wrp = tid >> 5;
    int inc = cnt;
    #pragma unroll
    for (int o = 1; o < 32; o <<= 1) {
        int v = __shfl_up_sync(0xFFFFFFFFu, inc, o);
        if (lane >= o) inc += v;
    }
    if (lane == 31) s_wsum[wrp] = inc;
    __syncthreads();
    int wbase = 0;
    for (int w = 0; w < wrp; w++) wbase += s_wsum[w];
    int r = wbase + inc - cnt;   // exclusive prefix for this thread's chunk
    #pragma unroll
    for (int j = 0; j < 16; j++) {
        s_rank[pbase + j] = (unsigned short)r;
        r += (int)s_fmask[pbase + j];
    }
    if (tid == BLK - 1) s_total = r;
    __syncthreads();

    // Pass 2: vectorized sweep. Superblock = 4 positions = 36 floats = 9 float4.
    float coord = 0.f, width = 0.f, bce = 0.f;
    const float4* p4 = (const float4*)prow;
    const float4* t4 = (const float4*)trow;
    for (int s = tid; s < M_DIM / 4; s += BLK) {
        float p[36], t[36];
        #pragma unroll
        for (int k = 0; k < 9; k++) {
            float4 v = __ldg(p4 + s * 9 + k);
            p[4 * k] = v.x; p[4 * k + 1] = v.y; p[4 * k + 2] = v.z; p[4 * k + 3] = v.w;
            float4 w = __ldg(t4 + s * 9 + k);
            t[4 * k] = w.x; t[4 * k + 1] = w.y; t[4 * k + 2] = w.z; t[4 * k + 3] = w.w;
        }
        const int pos0 = s * 4;
        uchar4  fmv = *(const uchar4*)(s_fmask + pos0);
        ushort4 rkv = *(const ushort4*)(s_rank + pos0);
        const unsigned char  fms[4] = {fmv.x, fmv.y, fmv.z, fmv.w};
        const unsigned short rks[4] = {rkv.x, rkv.y, rkv.z, rkv.w};
        #pragma unroll
        for (int q = 0; q < 4; q++) {
            const int b = q * 9;
            float m = (float)fms[q];
            float cs = fabsf(p[b] - t[b]) + fabsf(p[b + 1] - t[b + 1]) +
                       fabsf(p[b + 2] - t[b + 2]) + fabsf(p[b + 3] - t[b + 3]) +
                       fabsf(p[b + 4] - t[b + 4]) + fabsf(p[b + 5] - t[b + 5]);
            coord = fmaf(cs, m, coord);
            float ws = fabsf(p[b + 6] - t[b + 6]) + fabsf(p[b + 7] - t[b + 7]);
            width = fmaf(ws, m, width);
            float pc = fminf(fmaxf(p[b + 8], EPSF), 1.f - EPSF);
            float tv = t[b + 8];
            bce -= tv * __log2f(pc) + (1.f - tv) * __log2f(1.f - pc);
            if (fms[q]) s_comp[rks[q]] = make_float2(p[b + 4], p[b + 5]);
        }
    }
    __syncthreads();

    // Continuity: adjacent compacted valid pairs.
    float cont = 0.f;
    const int total = s_total;
    for (int j = tid; j + 1 < total; j += BLK) {
        float2 a = s_comp[j], c = s_comp[j + 1];
        cont += fabsf(a.x - c.x) + fabsf(a.y - c.y);
    }
    cont *= 0.5f;

    // Block reduce 4 partials, atomics into double accumulators.
    float vals[4] = {coord, width, bce, cont};
    const int dst[4] = {0, 1, 3, 4};
    #pragma unroll
    for (int v = 0; v < 4; v++) {
        float a = vals[v];
        #pragma unroll
        for (int o = 16; o; o >>= 1) a += __shfl_down_sync(0xFFFFFFFFu, a, o);
        if ((tid & 31) == 0) s_red[tid >> 5] = a;
        __syncthreads();
        if (tid == 0) {
            float ssum = 0.f;
            #pragma unroll
            for (int w = 0; w < BLK / 32; w++) ssum += s_red[w];
            atomicAdd(&g_acc[dst[v]], (double)ssum);
        }
        __syncthreads();
    }
    if (tid == 0) atomicAdd(&g_acc[2], (double)total);
}

__global__ void finalize_kernel(float* out) {
    double nv = g_acc[2];
    double coord = 0.0, width = 0.0;
    if (nv > 0.0) {
        coord = g_acc[0] / fmax(nv * 6.0, 1.0);
        width = g_acc[1] / fmax(nv * 2.0, 1.0);
    }
    double bce  = g_acc[3] * 0.6931471805599453 / ((double)B_DIM * (double)M_DIM);
    double cont = g_acc[4] / (double)B_DIM;
    double rc   = g_acc[5] / ((double)B_DIM * 128.0 * 128.0);
    out[0] = (float)(coord + width + 2.0 * bce + 0.2 * cont + 0.1 * rc);
}

extern "C" void kernel_launch(void* const* d_in, const int* in_sizes, int n_in,
                              void* d_out, int out_size) {
    const float* pred = (const float*)d_in[0];
    const float* tgt  = (const float*)d_in[1];
    const float* rec  = (const float*)d_in[2];
    const float* img  = (const float*)d_in[3];

    zero_kernel<<<1, 32>>>();
    fused_kernel<<<ROW_BLOCKS + RECON_BLOCKS, BLK>>>(pred, tgt, rec, img);
    finalize_kernel<<<1, 1>>>((float*)d_out);
}